// round 11
// baseline (speedup 1.0000x reference)
#include <cuda_runtime.h>
#include <cstdint>
#include <cstddef>

#define B_ 4
#define N_ 8192
#define K_ 32
#define C_ 64

#define RS 144   // attn/h row stride in floats (4 pts * 36) per group
#define PS 36    // per-point column-slot stride in floats
#define WS 68    // padded stride for fo / g1

typedef unsigned long long u64;

__device__ __forceinline__ void fma2(u64& d, u64 a, u64 b) {
    asm("fma.rn.f32x2 %0, %1, %2, %0;" : "+l"(d) : "l"(a), "l"(b));
}
__device__ __forceinline__ u64 add2(u64 a, u64 b) {
    u64 r; asm("add.rn.f32x2 %0, %1, %2;" : "=l"(r) : "l"(a), "l"(b)); return r;
}
__device__ __forceinline__ u64 pk2(float lo, float hi) {
    u64 r; asm("mov.b64 %0, {%1, %2};" : "=l"(r) : "f"(lo), "f"(hi)); return r;
}
__device__ __forceinline__ void upk2(float& lo, float& hi, u64 v) {
    asm("mov.b64 {%0, %1}, %2;" : "=f"(lo), "=f"(hi) : "l"(v));
}
#define GBAR() asm volatile("bar.sync %0, 256;" :: "r"(grp + 1) : "memory")

// precomputed linear parts: Ga = Wa_f @ f + b_attn, G1 = W1_f @ f + b1
__device__ float g_Ga[(size_t)B_ * N_ * C_];
__device__ float g_G1[(size_t)B_ * N_ * C_];

// constant weights (warp-uniform access in main kernel)
__constant__ float  cW2[4096];   // [k][o]
__constant__ float4 cWap[64];    // W_attn cols 0..2
__constant__ float4 cW1p[64];    // W1 cols 0..2
__device__ float  g_sW2[4096];
__device__ float4 g_sWap[64];
__device__ float4 g_sW1p[64];

__global__ void stage_weights(const float* __restrict__ W2,
                              const float* __restrict__ Wa,
                              const float* __restrict__ W1) {
    const int i = blockIdx.x * blockDim.x + threadIdx.x;
    if (i < 4096) g_sW2[(i & 63) * 64 + (i >> 6)] = W2[i];
    if (i < 64) {
        g_sWap[i] = make_float4(Wa[i*67], Wa[i*67+1], Wa[i*67+2], 0.f);
        g_sW1p[i] = make_float4(W1[i*67], W1[i*67+1], W1[i*67+2], 0.f);
    }
}

// ---------------------------------------------------------------------------
// precompute kernel: 64 points per block, 256 threads
// ---------------------------------------------------------------------------
__global__ void __launch_bounds__(256) precompute_kernel(
    const float* __restrict__ f,
    const float* __restrict__ Wa, const float* __restrict__ ba,
    const float* __restrict__ W1, const float* __restrict__ b1)
{
    __shared__ float4 Wa4[1024];
    __shared__ float4 W14[1024];
    __shared__ float bsa[64], bs1[64];
    const int tid = threadIdx.x;
    const int b = blockIdx.y, n0 = blockIdx.x * 64;

    for (int i = tid; i < 1024; i += 256) {
        int c = i >> 4, j = (i & 15) * 4;
        Wa4[i] = make_float4(Wa[c*67+3+j], Wa[c*67+4+j], Wa[c*67+5+j], Wa[c*67+6+j]);
        W14[i] = make_float4(W1[c*67+3+j], W1[c*67+4+j], W1[c*67+5+j], W1[c*67+6+j]);
    }
    if (tid < 64) { bsa[tid] = ba[tid]; bs1[tid] = b1[tid]; }
    __syncthreads();

    const int nl = tid & 63, c0 = (tid >> 6) * 16;
    const int n = n0 + nl;
    float x[64];
#pragma unroll
    for (int i = 0; i < 64; i++) x[i] = f[((size_t)b * 64 + i) * N_ + n];

    float oA[16], oB[16];
#pragma unroll
    for (int cc = 0; cc < 16; cc++) {
        const int c = c0 + cc;
        float accA = bsa[c], accB = bs1[c];
#pragma unroll
        for (int q = 0; q < 16; q++) {
            float4 w = Wa4[c * 16 + q];
            float4 v = W14[c * 16 + q];
            accA += w.x*x[4*q] + w.y*x[4*q+1] + w.z*x[4*q+2] + w.w*x[4*q+3];
            accB += v.x*x[4*q] + v.y*x[4*q+1] + v.z*x[4*q+2] + v.w*x[4*q+3];
        }
        oA[cc] = accA; oB[cc] = accB;
    }
    float4* dstA = (float4*)(g_Ga + ((size_t)b * N_ + n) * 64 + c0);
    float4* dstB = (float4*)(g_G1 + ((size_t)b * N_ + n) * 64 + c0);
#pragma unroll
    for (int q = 0; q < 4; q++) {
        dstA[q] = make_float4(oA[4*q], oA[4*q+1], oA[4*q+2], oA[4*q+3]);
        dstB[q] = make_float4(oB[4*q], oB[4*q+1], oB[4*q+2], oB[4*q+3]);
    }
}

// ---------------------------------------------------------------------------
// per-group smem layout (floats); group stride 28464, 2 groups = 227,712 B
// ---------------------------------------------------------------------------
#define GA_ATTN 0          // 64*144
#define GA_HBUF 9216       // 64*144
#define GA_SCR  18432      // 128*68
#define GA_FP0  27136      // 4*68
#define GA_FP1  27408
#define GA_G1   27680
#define GA_DP0  27952
#define GA_DP1  28080
#define GA_DP2  28208
#define GA_IDX  28336      // int[128]
#define GRP_FLOATS 28464
#define SMEM_FLOATS (2 * GRP_FLOATS)
#define SMEM_BYTES (SMEM_FLOATS * 4)

// ---------------------------------------------------------------------------
// main kernel: 8 points / block, 512 threads = 2 independent 256-thread
// groups (named barriers) x 4 points each
// ---------------------------------------------------------------------------
__global__ void __launch_bounds__(512, 1) lpamlp_main_kernel(
    const float* __restrict__ p, const int* __restrict__ idx,
    const float* __restrict__ f,
    const float* __restrict__ b2,
    const float* __restrict__ Wf1, const float* __restrict__ bf1,
    const float* __restrict__ Wf2, const float* __restrict__ bf2,
    float* __restrict__ out_f2)
{
    extern __shared__ float smbase[];
    const int tid = threadIdx.x;
    const int grp = tid >> 8;              // 0 or 1
    const int gtid = tid & 255;
    const int gw = gtid >> 5, lane = tid & 31;

    float* sm = smbase + grp * GRP_FLOATS;
    float*  attn   = sm + GA_ATTN;
    float*  hbuf   = sm + GA_HBUF;
    float*  scr    = sm + GA_SCR;            // scratch: 128 rows x 68
    float*  fp0    = sm + GA_FP0;
    float*  fp1    = sm + GA_FP1;
    float*  g1_sh  = sm + GA_G1;
    float*  dp0    = sm + GA_DP0;
    float*  dp1    = sm + GA_DP1;
    float*  dp2    = sm + GA_DP2;
    int*    idx_sh = (int*)(sm + GA_IDX);

    const int b = blockIdx.y;
    const int n0 = blockIdx.x * 8 + grp * 4;

    // ---- pre: idx + dp per column (128 cols per group) ----
    if (gtid < 128) {
        const int col = gtid, pt = col >> 5, k = col & 31;
        const int n = n0 + pt;
        const int nb = idx[((size_t)b * N_ + n) * K_ + k];
        idx_sh[col] = nb;
        const float* pj = p + ((size_t)b * N_ + nb) * 3;
        const float* pc = p + ((size_t)b * N_ + n) * 3;
        dp0[col] = pj[0] - pc[0];
        dp1[col] = pj[1] - pc[1];
        dp2[col] = pj[2] - pc[2];
    }
    GBAR();

    const int g_nbr = lane >> 4, g_chk = lane & 15;

    // ---- gather Ga rows -> scratch (line-cooperative, 16 cols per warp) ----
#pragma unroll
    for (int t = 0; t < 8; t++) {
        const int col = gw * 16 + 2 * t + g_nbr;
        const int nb = idx_sh[col];
        float4 v = *(const float4*)(g_Ga + ((size_t)b * N_ + nb) * 64 + g_chk * 4);
        *(float4*)(scr + col * 68 + g_chk * 4) = v;
    }
    GBAR();

    // ---- transform: attn[c][col] = Ga + wa.dp ----
    {
        const int col = gtid & 127, sub = gtid >> 7;
        const int pt = col >> 5, k = col & 31;
        const int coff = pt * PS + k;
        const float d0 = dp0[col], d1 = dp1[col], d2 = dp2[col];
#pragma unroll
        for (int c4 = 0; c4 < 8; c4++) {
            float4 g = *(const float4*)(scr + col * 68 + sub * 32 + c4 * 4);
            const float gv[4] = {g.x, g.y, g.z, g.w};
#pragma unroll
            for (int j = 0; j < 4; j++) {
                const int c = sub * 32 + c4 * 4 + j;
                const float4 wa = cWap[c];
                attn[c * RS + coff] = gv[j] + wa.x*d0 + wa.y*d1 + wa.z*d2;
            }
        }
    }
    GBAR();

    // ---- gather G1 rows -> scratch ----
#pragma unroll
    for (int t = 0; t < 8; t++) {
        const int col = gw * 16 + 2 * t + g_nbr;
        const int nb = idx_sh[col];
        float4 v = *(const float4*)(g_G1 + ((size_t)b * N_ + nb) * 64 + g_chk * 4);
        *(float4*)(scr + col * 68 + g_chk * 4) = v;
    }
    GBAR();

    // ---- transform: hbuf[c][col] = relu(G1 + w1.dp) ----
    {
        const int col = gtid & 127, sub = gtid >> 7;
        const int pt = col >> 5, k = col & 31;
        const int coff = pt * PS + k;
        const float d0 = dp0[col], d1 = dp1[col], d2 = dp2[col];
#pragma unroll
        for (int c4 = 0; c4 < 8; c4++) {
            float4 g = *(const float4*)(scr + col * 68 + sub * 32 + c4 * 4);
            const float gv[4] = {g.x, g.y, g.z, g.w};
#pragma unroll
            for (int j = 0; j < 4; j++) {
                const int c = sub * 32 + c4 * 4 + j;
                const float4 w1 = cW1p[c];
                hbuf[c * RS + coff] = fmaxf(gv[j] + w1.x*d0 + w1.y*d1 + w1.z*d2, 0.f);
            }
        }
    }
    GBAR();

    // ---- phase S: softmax over neighbors, 1 item (c, pt) per thread ----
    {
        const int c = gtid >> 2, pt2 = gtid & 3;
        float4* row = (float4*)(attn + c * RS + pt2 * PS);
        float4 v[8];
#pragma unroll
        for (int q = 0; q < 8; q++) v[q] = row[q];
        float m = -1e30f;
#pragma unroll
        for (int q = 0; q < 8; q++)
            m = fmaxf(m, fmaxf(fmaxf(v[q].x, v[q].y), fmaxf(v[q].z, v[q].w)));
        float s = 0.f;
#pragma unroll
        for (int q = 0; q < 8; q++) {
            v[q].x = __expf(v[q].x - m); v[q].y = __expf(v[q].y - m);
            v[q].z = __expf(v[q].z - m); v[q].w = __expf(v[q].w - m);
            s += (v[q].x + v[q].y) + (v[q].z + v[q].w);
        }
        const float inv = __fdividef(1.f, s);
#pragma unroll
        for (int q = 0; q < 8; q++) {
            v[q].x *= inv; v[q].y *= inv; v[q].z *= inv; v[q].w *= inv;
            row[q] = v[q];
        }
    }
    GBAR();

    // ---- phase M: partial fo = sum_k(ca .* W2@h); W2 from constant ----
    {
        const int chan0 = (gw >> 1) * 16;
        const int khalf = gw & 1;
        float* fop = khalf ? fp1 : fp0;
        const int ptl = lane >> 3, q = lane & 7;
        const int colbase = ptl * PS + q * 4;

        u64 acc2[8][4];
#pragma unroll
        for (int a = 0; a < 8; a++)
#pragma unroll
            for (int j = 0; j < 4; j++) acc2[a][j] = 0ull;

        const float* hrow = hbuf + khalf * 32 * RS;
        const float* wrow = cW2 + khalf * 32 * 64 + chan0;
#pragma unroll 4
        for (int kk = 0; kk < 32; kk++) {
            const ulonglong2 aA = *(const ulonglong2*)(wrow + kk * 64);
            const ulonglong2 aB = *(const ulonglong2*)(wrow + kk * 64 + 4);
            const ulonglong2 aC = *(const ulonglong2*)(wrow + kk * 64 + 8);
            const ulonglong2 aD = *(const ulonglong2*)(wrow + kk * 64 + 12);
            const float4 bv = *(const float4*)(hrow + kk * RS + colbase);
            const u64 bb0 = pk2(bv.x, bv.x), bb1 = pk2(bv.y, bv.y);
            const u64 bb2 = pk2(bv.z, bv.z), bb3 = pk2(bv.w, bv.w);
            fma2(acc2[0][0], aA.x, bb0); fma2(acc2[0][1], aA.x, bb1);
            fma2(acc2[0][2], aA.x, bb2); fma2(acc2[0][3], aA.x, bb3);
            fma2(acc2[1][0], aA.y, bb0); fma2(acc2[1][1], aA.y, bb1);
            fma2(acc2[1][2], aA.y, bb2); fma2(acc2[1][3], aA.y, bb3);
            fma2(acc2[2][0], aB.x, bb0); fma2(acc2[2][1], aB.x, bb1);
            fma2(acc2[2][2], aB.x, bb2); fma2(acc2[2][3], aB.x, bb3);
            fma2(acc2[3][0], aB.y, bb0); fma2(acc2[3][1], aB.y, bb1);
            fma2(acc2[3][2], aB.y, bb2); fma2(acc2[3][3], aB.y, bb3);
            fma2(acc2[4][0], aC.x, bb0); fma2(acc2[4][1], aC.x, bb1);
            fma2(acc2[4][2], aC.x, bb2); fma2(acc2[4][3], aC.x, bb3);
            fma2(acc2[5][0], aC.y, bb0); fma2(acc2[5][1], aC.y, bb1);
            fma2(acc2[5][2], aC.y, bb2); fma2(acc2[5][3], aC.y, bb3);
            fma2(acc2[6][0], aD.x, bb0); fma2(acc2[6][1], aD.x, bb1);
            fma2(acc2[6][2], aD.x, bb2); fma2(acc2[6][3], aD.x, bb3);
            fma2(acc2[7][0], aD.y, bb0); fma2(acc2[7][1], aD.y, bb1);
            fma2(acc2[7][2], aD.y, bb2); fma2(acc2[7][3], aD.y, bb3);
        }

#pragma unroll
        for (int a = 0; a < 8; a++) {
            const int ce = chan0 + 2 * a, co = ce + 1;
            const float4 ue = *(const float4*)(attn + ce * RS + colbase);
            const float4 uo = *(const float4*)(attn + co * RS + colbase);
            u64 part = 0ull;
            fma2(part, pk2(ue.x, uo.x), acc2[a][0]);
            fma2(part, pk2(ue.y, uo.y), acc2[a][1]);
            fma2(part, pk2(ue.z, uo.z), acc2[a][2]);
            fma2(part, pk2(ue.w, uo.w), acc2[a][3]);
#pragma unroll
            for (int o = 1; o < 8; o <<= 1)
                part = add2(part, (u64)__shfl_xor_sync(0xffffffffu,
                                    (unsigned long long)part, o));
            if (q == 0) {
                float pe, po;
                upk2(pe, po, part);
                fop[ptl * WS + ce] = pe;
                fop[ptl * WS + co] = po;
            }
        }
    }
    GBAR();

    // ---- phase F: combine partials, FFN with direct-global weights ----
    {
        const int c = gtid >> 2, fpt = gtid & 3;
        const int n = n0 + fpt;

        float fo = fp0[fpt * WS + c] + fp1[fpt * WS + c] + __ldg(b2 + c)
                 + __ldg(f + ((size_t)b * 64 + c) * N_ + n);
        fo = fmaxf(fo, 0.f);
        fp0[fpt * WS + c] = fo;              // fp0 becomes final fo
        GBAR();

        float g1 = __ldg(bf1 + c);
#pragma unroll
        for (int i4 = 0; i4 < 64; i4 += 4) {
            const float4 fv = *(const float4*)(fp0 + fpt * WS + i4);
            const float4 wv = __ldg((const float4*)(Wf1 + c * 64 + i4));
            g1 += fv.x*wv.x + fv.y*wv.y + fv.z*wv.z + fv.w*wv.w;
        }
        g1_sh[fpt * WS + c] = fmaxf(g1, 0.f);
        GBAR();

        float g2 = __ldg(bf2 + c);
#pragma unroll
        for (int i4 = 0; i4 < 64; i4 += 4) {
            const float4 gv = *(const float4*)(g1_sh + fpt * WS + i4);
            const float4 wv = __ldg((const float4*)(Wf2 + c * 64 + i4));
            g2 += gv.x*wv.x + gv.y*wv.y + gv.z*wv.z + gv.w*wv.w;
        }
        out_f2[((size_t)b * 64 + c) * N_ + n] =
            fmaxf(g2 + fp0[fpt * WS + c], 0.f);
    }
}

// ---------------------------------------------------------------------------
// launch
// ---------------------------------------------------------------------------
extern "C" void kernel_launch(void* const* d_in, const int* in_sizes, int n_in,
                              void* d_out, int out_size)
{
    const float* p      = (const float*)d_in[0];
    const float* f      = (const float*)d_in[1];
    const int*   idx    = (const int*)d_in[2];
    const float* W_attn = (const float*)d_in[3];
    const float* b_attn = (const float*)d_in[4];
    const float* W1     = (const float*)d_in[5];
    const float* b1     = (const float*)d_in[6];
    const float* W2     = (const float*)d_in[7];
    const float* b2     = (const float*)d_in[8];
    const float* Wf1    = (const float*)d_in[9];
    const float* bf1    = (const float*)d_in[10];
    const float* Wf2    = (const float*)d_in[11];
    const float* bf2    = (const float*)d_in[12];

    float* out = (float*)d_out;
    const int psz = B_ * N_ * 3;
    const int fsz = B_ * C_ * N_;

    float* out_f2 = out;
    if (out_size >= psz + fsz) {
        cudaMemcpyAsync(out, p, (size_t)psz * sizeof(float),
                        cudaMemcpyDeviceToDevice);
        out_f2 = out + psz;
    }

    stage_weights<<<16, 256>>>(W2, W_attn, W1);
    void *sW2, *sWap, *sW1p;
    cudaGetSymbolAddress(&sW2, g_sW2);
    cudaGetSymbolAddress(&sWap, g_sWap);
    cudaGetSymbolAddress(&sW1p, g_sW1p);
    cudaMemcpyToSymbolAsync(cW2, sW2, 4096 * sizeof(float), 0,
                            cudaMemcpyDeviceToDevice, 0);
    cudaMemcpyToSymbolAsync(cWap, sWap, 64 * sizeof(float4), 0,
                            cudaMemcpyDeviceToDevice, 0);
    cudaMemcpyToSymbolAsync(cW1p, sW1p, 64 * sizeof(float4), 0,
                            cudaMemcpyDeviceToDevice, 0);

    precompute_kernel<<<dim3(N_ / 64, B_), 256>>>(f, W_attn, b_attn, W1, b1);

    cudaFuncSetAttribute(lpamlp_main_kernel,
                         cudaFuncAttributeMaxDynamicSharedMemorySize, SMEM_BYTES);
    lpamlp_main_kernel<<<dim3(N_ / 8, B_), 512, SMEM_BYTES>>>(
        p, idx, f, b2, Wf1, bf1, Wf2, bf2, out_f2);
}

// round 12
// speedup vs baseline: 1.2484x; 1.2484x over previous
#include <cuda_runtime.h>
#include <cstdint>
#include <cstddef>

#define B_ 4
#define N_ 8192
#define K_ 32
#define C_ 64

#define RS 288   // attn/h row stride in floats (8 pts * 36)
#define PS 36    // per-point column-slot stride in floats
#define WS 68    // padded stride for fo / g1

typedef unsigned long long u64;

__device__ __forceinline__ void fma2(u64& d, u64 a, u64 b) {
    asm("fma.rn.f32x2 %0, %1, %2, %0;" : "+l"(d) : "l"(a), "l"(b));
}
__device__ __forceinline__ u64 add2(u64 a, u64 b) {
    u64 r; asm("add.rn.f32x2 %0, %1, %2;" : "=l"(r) : "l"(a), "l"(b)); return r;
}
__device__ __forceinline__ u64 pk2(float lo, float hi) {
    u64 r; asm("mov.b64 %0, {%1, %2};" : "=l"(r) : "f"(lo), "f"(hi)); return r;
}
__device__ __forceinline__ void upk2(float& lo, float& hi, u64 v) {
    asm("mov.b64 {%0, %1}, %2;" : "=f"(lo), "=f"(hi) : "l"(v));
}
__device__ __forceinline__ uint32_t smem_u32(const void* p) {
    uint32_t a;
    asm("{ .reg .u64 t; cvta.to.shared.u64 t, %1; cvt.u32.u64 %0, t; }" : "=r"(a) : "l"(p));
    return a;
}
#define CP_ASYNC16(dst, src) \
    asm volatile("cp.async.cg.shared.global [%0], [%1], 16;" :: "r"(dst), "l"(src) : "memory")
#define CP_COMMIT() asm volatile("cp.async.commit_group;" ::: "memory")
#define CP_WAIT(n)  asm volatile("cp.async.wait_group %0;" :: "n"(n) : "memory")

// precomputed linear parts: Ga = Wa_f @ f + b_attn, G1 = W1_f @ f + b1
__device__ float g_Ga[(size_t)B_ * N_ * C_];
__device__ float g_G1[(size_t)B_ * N_ * C_];

// constant weights (warp-uniform access in main kernel)
__constant__ float  cW2[4096];   // [k][o]
__constant__ float4 cWap[64];    // W_attn cols 0..2
__constant__ float4 cW1p[64];    // W1 cols 0..2
__device__ float  g_sW2[4096];
__device__ float4 g_sWap[64];
__device__ float4 g_sW1p[64];

__global__ void stage_weights(const float* __restrict__ W2,
                              const float* __restrict__ Wa,
                              const float* __restrict__ W1) {
    const int i = blockIdx.x * blockDim.x + threadIdx.x;
    if (i < 4096) g_sW2[(i & 63) * 64 + (i >> 6)] = W2[i];
    if (i < 64) {
        g_sWap[i] = make_float4(Wa[i*67], Wa[i*67+1], Wa[i*67+2], 0.f);
        g_sW1p[i] = make_float4(W1[i*67], W1[i*67+1], W1[i*67+2], 0.f);
    }
}

// ---------------------------------------------------------------------------
// precompute kernel: 64 points per block, 256 threads
// ---------------------------------------------------------------------------
__global__ void __launch_bounds__(256) precompute_kernel(
    const float* __restrict__ f,
    const float* __restrict__ Wa, const float* __restrict__ ba,
    const float* __restrict__ W1, const float* __restrict__ b1)
{
    __shared__ float4 Wa4[1024];
    __shared__ float4 W14[1024];
    __shared__ float bsa[64], bs1[64];
    const int tid = threadIdx.x;
    const int b = blockIdx.y, n0 = blockIdx.x * 64;

    for (int i = tid; i < 1024; i += 256) {
        int c = i >> 4, j = (i & 15) * 4;
        Wa4[i] = make_float4(Wa[c*67+3+j], Wa[c*67+4+j], Wa[c*67+5+j], Wa[c*67+6+j]);
        W14[i] = make_float4(W1[c*67+3+j], W1[c*67+4+j], W1[c*67+5+j], W1[c*67+6+j]);
    }
    if (tid < 64) { bsa[tid] = ba[tid]; bs1[tid] = b1[tid]; }
    __syncthreads();

    const int nl = tid & 63, c0 = (tid >> 6) * 16;
    const int n = n0 + nl;
    float x[64];
#pragma unroll
    for (int i = 0; i < 64; i++) x[i] = f[((size_t)b * 64 + i) * N_ + n];

    float oA[16], oB[16];
#pragma unroll
    for (int cc = 0; cc < 16; cc++) {
        const int c = c0 + cc;
        float accA = bsa[c], accB = bs1[c];
#pragma unroll
        for (int q = 0; q < 16; q++) {
            float4 w = Wa4[c * 16 + q];
            float4 v = W14[c * 16 + q];
            accA += w.x*x[4*q] + w.y*x[4*q+1] + w.z*x[4*q+2] + w.w*x[4*q+3];
            accB += v.x*x[4*q] + v.y*x[4*q+1] + v.z*x[4*q+2] + v.w*x[4*q+3];
        }
        oA[cc] = accA; oB[cc] = accB;
    }
    float4* dstA = (float4*)(g_Ga + ((size_t)b * N_ + n) * 64 + c0);
    float4* dstB = (float4*)(g_G1 + ((size_t)b * N_ + n) * 64 + c0);
#pragma unroll
    for (int q = 0; q < 4; q++) {
        dstA[q] = make_float4(oA[4*q], oA[4*q+1], oA[4*q+2], oA[4*q+3]);
        dstB[q] = make_float4(oB[4*q], oB[4*q+1], oB[4*q+2], oB[4*q+3]);
    }
}

// ---------------------------------------------------------------------------
// smem layout (floats)
// ---------------------------------------------------------------------------
#define O_ATTN 0          // 64*288
#define O_HBUF 18432      // 64*288
#define O_SCR  36864      // bufA 128*68 | bufB 128*68 = 17408
#define O_FP0  54272      // 8*68
#define O_FP1  54816
#define O_G1   55360
#define O_DP0  55904
#define O_DP1  56160
#define O_DP2  56416
#define O_IDX  56672      // int[256]
#define SMEM_FLOATS 56928
#define SMEM_BYTES (SMEM_FLOATS * 4)

// ---------------------------------------------------------------------------
// main kernel: 8 points / block, 512 threads, cp.async double-buffered gather
// ---------------------------------------------------------------------------
__global__ void __launch_bounds__(512, 1) lpamlp_main_kernel(
    const float* __restrict__ p, const int* __restrict__ idx,
    const float* __restrict__ f,
    const float* __restrict__ b2,
    const float* __restrict__ Wf1, const float* __restrict__ bf1,
    const float* __restrict__ Wf2, const float* __restrict__ bf2,
    float* __restrict__ out_f2)
{
    extern __shared__ float sm[];
    float*  attn   = sm + O_ATTN;
    float*  hbuf   = sm + O_HBUF;
    float*  bufA   = sm + O_SCR;
    float*  bufB   = sm + O_SCR + 8704;
    float*  fp0    = sm + O_FP0;
    float*  fp1    = sm + O_FP1;
    float*  g1_sh  = sm + O_G1;
    float*  dp0    = sm + O_DP0;
    float*  dp1    = sm + O_DP1;
    float*  dp2    = sm + O_DP2;
    int*    idx_sh = (int*)(sm + O_IDX);

    const int tid = threadIdx.x;
    const int b = blockIdx.y, n0 = blockIdx.x * 8;
    const int w = tid >> 5, lane = tid & 31;

    const uint32_t bufA_u = smem_u32(bufA);
    const uint32_t bufB_u = smem_u32(bufB);
    const float* GaB = g_Ga + (size_t)b * N_ * 64;
    const float* G1B = g_G1 + (size_t)b * N_ * 64;

    // ---- pre: idx + dp per column ----
    if (tid < 256) {
        const int col = tid, pt = col >> 5, k = col & 31;
        const int n = n0 + pt;
        const int nb = idx[((size_t)b * N_ + n) * K_ + k];
        idx_sh[col] = nb;
        const float* pj = p + ((size_t)b * N_ + nb) * 3;
        const float* pc = p + ((size_t)b * N_ + n) * 3;
        dp0[col] = pj[0] - pc[0];
        dp1[col] = pj[1] - pc[1];
        dp2[col] = pj[2] - pc[2];
    }
    __syncthreads();

    const int g_nbr = lane >> 4, g_chk = lane & 15;

    // issue helper (4 cp.async of 16B per thread = one 128-col half)
#define ISSUE_HALF(srcB, bufU, half)                                         \
    do {                                                                     \
        _Pragma("unroll")                                                    \
        for (int t = 0; t < 4; t++) {                                        \
            const int lcol = w * 8 + 2 * t + g_nbr;                          \
            const int nb = idx_sh[(half) * 128 + lcol];                      \
            const float* srcp = (srcB) + (size_t)nb * 64 + g_chk * 4;        \
            const uint32_t dst = (bufU) + (uint32_t)(lcol * 68 + g_chk * 4) * 4u; \
            CP_ASYNC16(dst, srcp);                                           \
        }                                                                    \
        CP_COMMIT();                                                         \
    } while (0)

    // transform helper bodies (attn / hbuf) for one 128-col half
    const int lcol = tid & 127, sub = tid >> 7;       // sub in 0..3

#define XFORM(buf, half, DSTARR, WVEC, RELU)                                 \
    do {                                                                     \
        const int col = (half) * 128 + lcol;                                 \
        const int pt = col >> 5, k = col & 31;                               \
        const int coff = pt * PS + k;                                        \
        const float d0 = dp0[col], d1 = dp1[col], d2 = dp2[col];             \
        _Pragma("unroll")                                                    \
        for (int q = 0; q < 4; q++) {                                        \
            float4 g = *(const float4*)((buf) + lcol * 68 + sub * 16 + q * 4); \
            const float gv[4] = {g.x, g.y, g.z, g.w};                        \
            _Pragma("unroll")                                                \
            for (int j = 0; j < 4; j++) {                                    \
                const int c = sub * 16 + q * 4 + j;                          \
                const float4 wv = WVEC[c];                                   \
                float val = gv[j] + wv.x*d0 + wv.y*d1 + wv.z*d2;             \
                if (RELU) val = fmaxf(val, 0.f);                             \
                DSTARR[c * RS + coff] = val;                                 \
            }                                                                \
        }                                                                    \
    } while (0)

    // ---- pipelined gathers + transforms ----
    ISSUE_HALF(GaB, bufA_u, 0);          // g0
    ISSUE_HALF(GaB, bufB_u, 1);          // g1
    CP_WAIT(1); __syncthreads();         // g0 done everywhere
    XFORM(bufA, 0, attn, cWap, false);
    __syncthreads();                     // bufA free
    ISSUE_HALF(G1B, bufA_u, 0);          // g2
    CP_WAIT(1); __syncthreads();         // g1 done
    XFORM(bufB, 1, attn, cWap, false);
    __syncthreads();                     // bufB free
    ISSUE_HALF(G1B, bufB_u, 1);          // g3
    CP_WAIT(1); __syncthreads();         // g2 done
    XFORM(bufA, 0, hbuf, cW1p, true);
    CP_WAIT(0); __syncthreads();         // g3 done
    XFORM(bufB, 1, hbuf, cW1p, true);
    __syncthreads();

    // ---- phase S: softmax over neighbors, 1 item (c, pt) per thread ----
    {
        const int c = tid >> 3, pt2 = tid & 7;
        float4* row = (float4*)(attn + c * RS + pt2 * PS);
        float4 v[8];
#pragma unroll
        for (int q = 0; q < 8; q++) v[q] = row[q];
        float m = -1e30f;
#pragma unroll
        for (int q = 0; q < 8; q++)
            m = fmaxf(m, fmaxf(fmaxf(v[q].x, v[q].y), fmaxf(v[q].z, v[q].w)));
        float s = 0.f;
#pragma unroll
        for (int q = 0; q < 8; q++) {
            v[q].x = __expf(v[q].x - m); v[q].y = __expf(v[q].y - m);
            v[q].z = __expf(v[q].z - m); v[q].w = __expf(v[q].w - m);
            s += (v[q].x + v[q].y) + (v[q].z + v[q].w);
        }
        const float inv = __fdividef(1.f, s);
#pragma unroll
        for (int q = 0; q < 8; q++) {
            v[q].x *= inv; v[q].y *= inv; v[q].z *= inv; v[q].w *= inv;
            row[q] = v[q];
        }
    }
    __syncthreads();

    // ---- phase M: partial fo = sum_k(ca .* W2@h); W2 from constant ----
    {
        const int chan0 = (w >> 2) * 16;
        const int half  = (w >> 1) & 1;
        const int khalf = w & 1;
        float* fop = khalf ? fp1 : fp0;
        const int ptl = lane >> 3, q = lane & 7;
        const int pt = half * 4 + ptl;
        const int colbase = pt * PS + q * 4;

        u64 acc2[8][4];
#pragma unroll
        for (int a = 0; a < 8; a++)
#pragma unroll
            for (int j = 0; j < 4; j++) acc2[a][j] = 0ull;

        const float* hrow = hbuf + khalf * 32 * RS;
        const float* wrow = cW2 + khalf * 32 * 64 + chan0;
#pragma unroll 4
        for (int kk = 0; kk < 32; kk++) {
            const ulonglong2 aA = *(const ulonglong2*)(wrow + kk * 64);
            const ulonglong2 aB = *(const ulonglong2*)(wrow + kk * 64 + 4);
            const ulonglong2 aC = *(const ulonglong2*)(wrow + kk * 64 + 8);
            const ulonglong2 aD = *(const ulonglong2*)(wrow + kk * 64 + 12);
            const float4 bv = *(const float4*)(hrow + kk * RS + colbase);
            const u64 bb0 = pk2(bv.x, bv.x), bb1 = pk2(bv.y, bv.y);
            const u64 bb2 = pk2(bv.z, bv.z), bb3 = pk2(bv.w, bv.w);
            fma2(acc2[0][0], aA.x, bb0); fma2(acc2[0][1], aA.x, bb1);
            fma2(acc2[0][2], aA.x, bb2); fma2(acc2[0][3], aA.x, bb3);
            fma2(acc2[1][0], aA.y, bb0); fma2(acc2[1][1], aA.y, bb1);
            fma2(acc2[1][2], aA.y, bb2); fma2(acc2[1][3], aA.y, bb3);
            fma2(acc2[2][0], aB.x, bb0); fma2(acc2[2][1], aB.x, bb1);
            fma2(acc2[2][2], aB.x, bb2); fma2(acc2[2][3], aB.x, bb3);
            fma2(acc2[3][0], aB.y, bb0); fma2(acc2[3][1], aB.y, bb1);
            fma2(acc2[3][2], aB.y, bb2); fma2(acc2[3][3], aB.y, bb3);
            fma2(acc2[4][0], aC.x, bb0); fma2(acc2[4][1], aC.x, bb1);
            fma2(acc2[4][2], aC.x, bb2); fma2(acc2[4][3], aC.x, bb3);
            fma2(acc2[5][0], aC.y, bb0); fma2(acc2[5][1], aC.y, bb1);
            fma2(acc2[5][2], aC.y, bb2); fma2(acc2[5][3], aC.y, bb3);
            fma2(acc2[6][0], aD.x, bb0); fma2(acc2[6][1], aD.x, bb1);
            fma2(acc2[6][2], aD.x, bb2); fma2(acc2[6][3], aD.x, bb3);
            fma2(acc2[7][0], aD.y, bb0); fma2(acc2[7][1], aD.y, bb1);
            fma2(acc2[7][2], aD.y, bb2); fma2(acc2[7][3], aD.y, bb3);
        }

#pragma unroll
        for (int a = 0; a < 8; a++) {
            const int ce = chan0 + 2 * a, co = ce + 1;
            const float4 ue = *(const float4*)(attn + ce * RS + colbase);
            const float4 uo = *(const float4*)(attn + co * RS + colbase);
            u64 part = 0ull;
            fma2(part, pk2(ue.x, uo.x), acc2[a][0]);
            fma2(part, pk2(ue.y, uo.y), acc2[a][1]);
            fma2(part, pk2(ue.z, uo.z), acc2[a][2]);
            fma2(part, pk2(ue.w, uo.w), acc2[a][3]);
#pragma unroll
            for (int o = 1; o < 8; o <<= 1)
                part = add2(part, (u64)__shfl_xor_sync(0xffffffffu,
                                    (unsigned long long)part, o));
            if (q == 0) {
                float pe, po;
                upk2(pe, po, part);
                fop[pt * WS + ce] = pe;
                fop[pt * WS + co] = po;
            }
        }
    }
    __syncthreads();

    // ---- phase F: combine partials, FFN with direct-global weights ----
    {
        const int c = tid >> 3, fpt = tid & 7;
        const int n = n0 + fpt;

        float fo = fp0[fpt * WS + c] + fp1[fpt * WS + c] + __ldg(b2 + c)
                 + __ldg(f + ((size_t)b * 64 + c) * N_ + n);
        fo = fmaxf(fo, 0.f);
        fp0[fpt * WS + c] = fo;              // fp0 becomes final fo
        __syncthreads();

        float g1 = __ldg(bf1 + c);
#pragma unroll
        for (int i4 = 0; i4 < 64; i4 += 4) {
            const float4 fv = *(const float4*)(fp0 + fpt * WS + i4);
            const float4 wv = __ldg((const float4*)(Wf1 + c * 64 + i4));
            g1 += fv.x*wv.x + fv.y*wv.y + fv.z*wv.z + fv.w*wv.w;
        }
        g1_sh[fpt * WS + c] = fmaxf(g1, 0.f);
        __syncthreads();

        float g2 = __ldg(bf2 + c);
#pragma unroll
        for (int i4 = 0; i4 < 64; i4 += 4) {
            const float4 gv = *(const float4*)(g1_sh + fpt * WS + i4);
            const float4 wv = __ldg((const float4*)(Wf2 + c * 64 + i4));
            g2 += gv.x*wv.x + gv.y*wv.y + gv.z*wv.z + gv.w*wv.w;
        }
        out_f2[((size_t)b * 64 + c) * N_ + n] =
            fmaxf(g2 + fp0[fpt * WS + c], 0.f);
    }
}

// ---------------------------------------------------------------------------
// launch
// ---------------------------------------------------------------------------
extern "C" void kernel_launch(void* const* d_in, const int* in_sizes, int n_in,
                              void* d_out, int out_size)
{
    const float* p      = (const float*)d_in[0];
    const float* f      = (const float*)d_in[1];
    const int*   idx    = (const int*)d_in[2];
    const float* W_attn = (const float*)d_in[3];
    const float* b_attn = (const float*)d_in[4];
    const float* W1     = (const float*)d_in[5];
    const float* b1     = (const float*)d_in[6];
    const float* W2     = (const float*)d_in[7];
    const float* b2     = (const float*)d_in[8];
    const float* Wf1    = (const float*)d_in[9];
    const float* bf1    = (const float*)d_in[10];
    const float* Wf2    = (const float*)d_in[11];
    const float* bf2    = (const float*)d_in[12];

    float* out = (float*)d_out;
    const int psz = B_ * N_ * 3;
    const int fsz = B_ * C_ * N_;

    float* out_f2 = out;
    if (out_size >= psz + fsz) {
        cudaMemcpyAsync(out, p, (size_t)psz * sizeof(float),
                        cudaMemcpyDeviceToDevice);
        out_f2 = out + psz;
    }

    stage_weights<<<16, 256>>>(W2, W_attn, W1);
    void *sW2, *sWap, *sW1p;
    cudaGetSymbolAddress(&sW2, g_sW2);
    cudaGetSymbolAddress(&sWap, g_sWap);
    cudaGetSymbolAddress(&sW1p, g_sW1p);
    cudaMemcpyToSymbolAsync(cW2, sW2, 4096 * sizeof(float), 0,
                            cudaMemcpyDeviceToDevice, 0);
    cudaMemcpyToSymbolAsync(cWap, sWap, 64 * sizeof(float4), 0,
                            cudaMemcpyDeviceToDevice, 0);
    cudaMemcpyToSymbolAsync(cW1p, sW1p, 64 * sizeof(float4), 0,
                            cudaMemcpyDeviceToDevice, 0);

    precompute_kernel<<<dim3(N_ / 64, B_), 256>>>(f, W_attn, b_attn, W1, b1);

    cudaFuncSetAttribute(lpamlp_main_kernel,
                         cudaFuncAttributeMaxDynamicSharedMemorySize, SMEM_BYTES);
    lpamlp_main_kernel<<<dim3(N_ / 8, B_), 512, SMEM_BYTES>>>(
        p, idx, f, b2, Wf1, bf1, Wf2, bf2, out_f2);
}